// round 7
// baseline (speedup 1.0000x reference)
#include <cuda_runtime.h>
#include <cuda_bf16.h>
#include <stdint.h>

#define NNODES 50000
#define NPAD   50048            // 391 * 128
#define NEDGES 800000
#define IN_DIM 256
#define HEADS  8
#define NH     512

// ---------------- device scratch ----------------
__device__ __align__(128) __nv_bfloat16 g_Ah[(size_t)NPAD*IN_DIM];
__device__ __align__(128) __nv_bfloat16 g_Al[(size_t)NPAD*IN_DIM];
__device__ __align__(128) __nv_bfloat16 g_Bth[NH*IN_DIM];
__device__ __align__(128) __nv_bfloat16 g_Btl[NH*IN_DIM];
__device__ __align__(128) float g_Wh[(size_t)NNODES*NH];      // 102.4 MB
__device__ __align__(128) float g_buf[(size_t)NEDGES*64];     // 204.8 MB msg buffer
__device__ __align__(16)  float g_s[NNODES*16];
__device__ unsigned g_mkey[16];
__device__ float g_Z[HEADS];
__device__ float g_gate[HEADS];
__device__ int g_cnt[NNODES];          // col counts (zeroed by scan1 for next run)
__device__ int g_rcnt[NNODES];         // row counts
__device__ int g_colptr[NNODES+1];
__device__ int g_rowptr[NNODES+1];
__device__ int g_cur[NNODES];          // col cursor
__device__ int g_curow[NNODES];        // row cursor
__device__ int g_bsum[2][256];
__device__ int g_srow[NEDGES];         // row of edge at CSC position p
__device__ int g_tgt[NEDGES];          // CSR position of edge at CSC position p

// ---------------- helpers ----------------
__device__ __forceinline__ unsigned fkey(float f){
    unsigned b = __float_as_uint(f);
    return (b & 0x80000000u) ? ~b : (b | 0x80000000u);
}
__device__ __forceinline__ float fdec(unsigned k){
    return (k & 0x80000000u) ? __uint_as_float(k ^ 0x80000000u) : __uint_as_float(~k);
}
__device__ __forceinline__ uint32_t s2u(const void* p){
    return (uint32_t)__cvta_generic_to_shared(p);
}
__device__ __forceinline__ void cpa16(uint32_t dst, const void* src){
    asm volatile("cp.async.cg.shared.global [%0], [%1], 16;" :: "r"(dst), "l"(src));
}
__device__ __forceinline__ void ldsm4(uint32_t* r, uint32_t addr){
    asm volatile("ldmatrix.sync.aligned.m8n8.x4.shared.b16 {%0,%1,%2,%3}, [%4];"
        : "=r"(r[0]), "=r"(r[1]), "=r"(r[2]), "=r"(r[3]) : "r"(addr));
}
__device__ __forceinline__ void mma_bf16(float* d, const uint32_t* a, uint32_t b0, uint32_t b1){
    asm volatile("mma.sync.aligned.m16n8k16.row.col.f32.bf16.bf16.f32 "
        "{%0,%1,%2,%3},{%4,%5,%6,%7},{%8,%9},{%0,%1,%2,%3};"
        : "+f"(d[0]), "+f"(d[1]), "+f"(d[2]), "+f"(d[3])
        : "r"(a[0]), "r"(a[1]), "r"(a[2]), "r"(a[3]), "r"(b0), "r"(b1));
}

// ---------------- fused setup: misc-zero, convert, prep, edge-counts ----------------
__global__ void k_setup(const float* __restrict__ x, const int* __restrict__ ei,
                        const float* __restrict__ W, const float* __restrict__ gate){
    int tid = blockIdx.x*blockDim.x + threadIdx.x;
    if (tid < 8)  g_Z[tid] = 0.f;
    if (tid < 16) g_mkey[tid] = 0u;
    if (tid == 0){
        float m = -1e30f;
        for (int h = 0; h < HEADS; h++) m = fmaxf(m, gate[h]);
        float ex[HEADS]; float z = 0.f;
        for (int h = 0; h < HEADS; h++){ ex[h] = __expf(gate[h]-m); z += ex[h]; }
        for (int h = 0; h < HEADS; h++) g_gate[h] = ex[h]/z;
    }
    // edge counts for CSC (cols) and CSR (rows)
    if (tid < NEDGES){
        atomicAdd(&g_cnt[ei[NEDGES + tid]], 1);
        atomicAdd(&g_rcnt[ei[tid]], 1);
    }
    // W transpose to Bt[n][d] bf16 hi/lo
    if (tid < NH*IN_DIM){
        int n = tid >> 8, d = tid & 255;
        int h = n >> 6, o = n & 63;
        float v = W[(size_t)h*IN_DIM*64 + d*64 + o];
        __nv_bfloat16 hb = __float2bfloat16(v);
        __nv_bfloat16 lb = __float2bfloat16(v - __bfloat162float(hb));
        g_Bth[tid] = hb;
        g_Btl[tid] = lb;
    }
    // x -> bf16 hi/lo, padded
    if (tid < NPAD*IN_DIM/4){
        int base = tid*4;
        int row = base / IN_DIM;
        float4 v = make_float4(0.f,0.f,0.f,0.f);
        if (row < NNODES) v = *reinterpret_cast<const float4*>(x + base);
        float vv[4] = {v.x, v.y, v.z, v.w};
        unsigned short hb[4], lb[4];
#pragma unroll
        for (int j = 0; j < 4; j++){
            __nv_bfloat16 h = __float2bfloat16(vv[j]);
            __nv_bfloat16 l = __float2bfloat16(vv[j] - __bfloat162float(h));
            hb[j] = __bfloat16_as_ushort(h);
            lb[j] = __bfloat16_as_ushort(l);
        }
        uint2 ph = make_uint2((unsigned)hb[0] | ((unsigned)hb[1]<<16),
                              (unsigned)hb[2] | ((unsigned)hb[3]<<16));
        uint2 pl = make_uint2((unsigned)lb[0] | ((unsigned)lb[1]<<16),
                              (unsigned)lb[2] | ((unsigned)lb[3]<<16));
        *reinterpret_cast<uint2*>(reinterpret_cast<char*>(g_Ah) + (size_t)base*2) = ph;
        *reinterpret_cast<uint2*>(reinterpret_cast<char*>(g_Al) + (size_t)base*2) = pl;
    }
}

// ---------------- dual CSC/CSR scans (blockIdx.y: 0=col, 1=row) ----------------
__global__ void k_scan1(){
    __shared__ int sd[256];
    int y = blockIdx.y;
    int* cnt = y ? g_rcnt : g_cnt;
    int tid = threadIdx.x;
    int i = blockIdx.x*256 + tid;
    int v = (i < NNODES) ? cnt[i] : 0;
    if (i < NNODES) cnt[i] = 0;            // re-zero for next run
    sd[tid] = v; __syncthreads();
    for (int off = 1; off < 256; off <<= 1){
        int t = (tid >= off) ? sd[tid - off] : 0;
        __syncthreads();
        sd[tid] += t;
        __syncthreads();
    }
    int* ptr = y ? g_rowptr : g_colptr;
    if (i < NNODES) ptr[i] = sd[tid] - v;
    if (tid == 255) g_bsum[y][blockIdx.x] = sd[255];
}
__global__ void k_scan2(){
    __shared__ int sd[256];
    int y = blockIdx.x;
    int tid = threadIdx.x;
    const int nb = (NNODES + 255)/256;
    int v = (tid < nb) ? g_bsum[y][tid] : 0;
    sd[tid] = v; __syncthreads();
    for (int off = 1; off < 256; off <<= 1){
        int t = (tid >= off) ? sd[tid - off] : 0;
        __syncthreads();
        sd[tid] += t;
        __syncthreads();
    }
    if (tid < nb) g_bsum[y][tid] = sd[tid] - v;
}
__global__ void k_scan3(){
    int y = blockIdx.y;
    int i = blockIdx.x*blockDim.x + threadIdx.x;
    int* ptr = y ? g_rowptr : g_colptr;
    int* cur = y ? g_curow  : g_cur;
    if (i < NNODES){
        int p = ptr[i] + g_bsum[y][i >> 8];
        ptr[i] = p;
        cur[i] = p;
    }
    if (i == 0) ptr[NNODES] = NEDGES;
}

// ---------------- big kernel: HMMA GEMM (4-stage pipe) + reorder in prologue ----------------
#define OFF_A    0                      // 4 stages x 8192
#define OFF_B    32768                  // 4 stages x 8192
#define OFF_BIAS 65536                  // 512 f
#define OFF_SA   67584                  // 1024 f
#define OFF_SSM  71680                  // 128*16 f
#define OFF_SMK  79872                  // 16 u32
#define SMEM_BIG 79936

__device__ __forceinline__ void load_tile(uint32_t dstbase, const __nv_bfloat16* __restrict__ src,
                                          int tid){
#pragma unroll
    for (int i = 0; i < 2; i++){
        int idx = tid + i*256;
        int r = idx >> 2, q = idx & 3;
        uint32_t off = (uint32_t)(r*64 + ((q ^ ((r >> 1) & 3)) << 4));
        cpa16(dstbase + off, src + (size_t)r*IN_DIM + q*8);
    }
}

__device__ __forceinline__ void gemm_compute(uint32_t sAb, uint32_t sBb,
                                             int wm, int wn, int lane, float d[4][4][4]){
#pragma unroll
    for (int ks = 0; ks < 2; ks++){
        uint32_t af[4][4], bf[2][4];
        int q = ks*2 + (lane >> 4);
#pragma unroll
        for (int mi = 0; mi < 4; mi++){
            int row = wm + mi*16 + (lane & 15);
            ldsm4(af[mi], sAb + row*64 + ((q ^ ((row >> 1) & 3)) << 4));
        }
#pragma unroll
        for (int bi = 0; bi < 2; bi++){
            int row = wn + bi*16 + (lane & 15);
            ldsm4(bf[bi], sBb + row*64 + ((q ^ ((row >> 1) & 3)) << 4));
        }
#pragma unroll
        for (int mi = 0; mi < 4; mi++)
#pragma unroll
            for (int ni = 0; ni < 4; ni++){
                int bi = ni >> 1, sub = ni & 1;
                mma_bf16(d[mi][ni], af[mi], bf[bi][sub], bf[bi][sub + 2]);
            }
    }
}

// grid = (4, 391)
__global__ __launch_bounds__(256,2) void k_big(const float* __restrict__ bias,
                                               const float* __restrict__ a_vec,
                                               const int* __restrict__ ei){
    extern __shared__ char smem[];
    uint32_t sb = s2u(smem);
    float*    s_bias = (float*)(smem + OFF_BIAS);
    float*    s_a    = (float*)(smem + OFF_SA);
    float*    s_sm   = (float*)(smem + OFF_SSM);
    unsigned* s_mk   = (unsigned*)(smem + OFF_SMK);

    int tid = threadIdx.x, wid = tid >> 5, lane = tid & 31;
    int wm = (wid >> 2)*64, wn = (wid & 3)*32;
    int m0 = blockIdx.y*128, n0 = blockIdx.x*128;

    for (int i = tid; i < 512;  i += 256) s_bias[i] = bias[i];
    for (int i = tid; i < 1024; i += 256) s_a[i]    = a_vec[i];
    for (int i = tid; i < 2048; i += 256) s_sm[i]   = 0.f;
    if (tid < 16) s_mk[tid] = 0u;

    float d[4][4][4];
#pragma unroll
    for (int mi = 0; mi < 4; mi++)
#pragma unroll
        for (int ni = 0; ni < 4; ni++)
#pragma unroll
            for (int k = 0; k < 4; k++) d[mi][ni][k] = 0.f;

    const __nv_bfloat16* Abase  = g_Ah  + (size_t)m0*IN_DIM;
    const __nv_bfloat16* Albase = g_Al  + (size_t)m0*IN_DIM;
    const __nv_bfloat16* Bbase  = g_Bth + (size_t)n0*IN_DIM;
    const __nv_bfloat16* Blbase = g_Btl + (size_t)n0*IN_DIM;

    // chunk c (0..23): pass p=c>>3 (0:Ah*Bh 1:Al*Bh 2:Ah*Bl), k-eighth q=c&7
#pragma unroll
    for (int c = 0; c < 3; c++){
        load_tile(sb + OFF_A + c*8192, Abase + c*32, tid);
        load_tile(sb + OFF_B + c*8192, Bbase + c*32, tid);
        asm volatile("cp.async.commit_group;" ::: "memory");
    }

    // CSC/CSR reorder: 512 edges per CTA, hidden behind first chunk loads
    {
        int cta = blockIdx.y*4 + blockIdx.x;
#pragma unroll
        for (int r = 0; r < 2; r++){
            int e = cta*512 + r*256 + tid;
            if (e < NEDGES){
                int row = ei[e], col = ei[NEDGES + e];
                int pos  = atomicAdd(&g_cur[col], 1);
                int rpos = atomicAdd(&g_curow[row], 1);
                g_srow[pos] = row;
                g_tgt[pos]  = rpos;
            }
        }
    }

    for (int c = 0; c < 24; c++){
        asm volatile("cp.async.wait_group 2;" ::: "memory");
        __syncthreads();
        int cn = c + 3;
        if (cn < 24){
            int p = cn >> 3, q = cn & 7;
            const __nv_bfloat16* As = ((p == 1) ? Albase : Abase) + q*32;
            const __nv_bfloat16* Bs = ((p == 2) ? Blbase : Bbase) + q*32;
            int st = cn & 3;
            load_tile(sb + OFF_A + st*8192, As, tid);
            load_tile(sb + OFF_B + st*8192, Bs, tid);
        }
        asm volatile("cp.async.commit_group;" ::: "memory");   // possibly empty group
        int st = c & 3;
        gemm_compute(sb + OFF_A + st*8192, sb + OFF_B + st*8192, wm, wn, lane, d);
    }

    // -------- epilogue: bias, Wh store, fused s-dots + node max --------
    int h = (n0 + wn) >> 6;
    const float* aS = s_a + h*128;
    const float* aD = s_a + h*128 + 64;
    float accS[4][2], accD[4][2];
#pragma unroll
    for (int mi = 0; mi < 4; mi++){ accS[mi][0]=accS[mi][1]=accD[mi][0]=accD[mi][1]=0.f; }

#pragma unroll
    for (int mi = 0; mi < 4; mi++){
#pragma unroll
        for (int ni = 0; ni < 4; ni++){
            int C = wn + ni*8 + (lane & 3)*2;
            int o = C & 63;
            float b0 = s_bias[n0 + C], b1 = s_bias[n0 + C + 1];
#pragma unroll
            for (int rr = 0; rr < 2; rr++){
                float v0 = d[mi][ni][rr*2 + 0] + b0;
                float v1 = d[mi][ni][rr*2 + 1] + b1;
                int R = wm + mi*16 + (lane >> 2) + rr*8;
                int gm = m0 + R;
                if (gm < NNODES){
                    float2 st2; st2.x = v0; st2.y = v1;
                    *reinterpret_cast<float2*>(g_Wh + (size_t)gm*NH + n0 + C) = st2;
                }
                accS[mi][rr] += v0*aS[o] + v1*aS[o+1];
                accD[mi][rr] += v0*aD[o] + v1*aD[o+1];
            }
        }
    }
#pragma unroll
    for (int mi = 0; mi < 4; mi++)
#pragma unroll
        for (int rr = 0; rr < 2; rr++){
            float vs = accS[mi][rr], vd = accD[mi][rr];
            vs += __shfl_xor_sync(0xffffffffu, vs, 1);
            vs += __shfl_xor_sync(0xffffffffu, vs, 2);
            vd += __shfl_xor_sync(0xffffffffu, vd, 1);
            vd += __shfl_xor_sync(0xffffffffu, vd, 2);
            if ((lane & 3) == 0){
                int R = wm + mi*16 + (lane >> 2) + rr*8;
                atomicAdd(&s_sm[R*16 + h],     vs);
                atomicAdd(&s_sm[R*16 + 8 + h], vd);
            }
        }
    __syncthreads();
    int h0 = n0 >> 6;
    for (int i = tid; i < 512; i += 256){
        int r = i >> 2, jj = i & 3;
        int j = h0 + (jj & 1) + (jj >> 1)*8;
        int gm = m0 + r;
        if (gm < NNODES){
            float v = s_sm[r*16 + j];
            g_s[gm*16 + j] = v;
            atomicMax(&s_mk[j], fkey(v));
        }
    }
    __syncthreads();
    if (tid < 4){
        int j = h0 + (tid & 1) + (tid >> 1)*8;
        unsigned k = s_mk[j];
        if (k) atomicMax(&g_mkey[j], k);
    }
}

// ---------------- per-head Z ----------------
__global__ void k_Z(const int* __restrict__ ei){
    __shared__ float sM[8];
    __shared__ float ssum[8];
    if (threadIdx.x < 8){
        float m = fdec(g_mkey[threadIdx.x]) + fdec(g_mkey[8 + threadIdx.x]);
        sM[threadIdx.x] = (m > 0.f) ? m : 0.01f*m;
        ssum[threadIdx.x] = 0.f;
    }
    __syncthreads();
    int p = blockIdx.x*blockDim.x + threadIdx.x;
    int row = ei[p], col = ei[NEDGES + p];
    float4 s0 = *reinterpret_cast<const float4*>(g_s + row*16);
    float4 s1 = *reinterpret_cast<const float4*>(g_s + row*16 + 4);
    float4 d0 = *reinterpret_cast<const float4*>(g_s + col*16 + 8);
    float4 d1 = *reinterpret_cast<const float4*>(g_s + col*16 + 12);
    float sv[8] = {s0.x,s0.y,s0.z,s0.w,s1.x,s1.y,s1.z,s1.w};
    float dv[8] = {d0.x,d0.y,d0.z,d0.w,d1.x,d1.y,d1.z,d1.w};
    float ex[8];
#pragma unroll
    for (int h = 0; h < 8; h++){
        float t = sv[h] + dv[h];
        t = (t > 0.f) ? t : 0.01f*t;
        ex[h] = __expf(t - sM[h]);
    }
#pragma unroll
    for (int h = 0; h < 8; h++)
#pragma unroll
        for (int off = 16; off; off >>= 1)
            ex[h] += __shfl_xor_sync(0xffffffffu, ex[h], off);
    if ((threadIdx.x & 31) == 0){
#pragma unroll
        for (int h = 0; h < 8; h++) atomicAdd(&ssum[h], ex[h]);
    }
    __syncthreads();
    if (threadIdx.x < 8) atomicAdd(&g_Z[threadIdx.x], ssum[threadIdx.x]);
}

// ---------------- phase A: messages to CSR-ordered buffer (no atomics) ----------------
__global__ __launch_bounds__(256) void k_msg(){
    __shared__ float sc[8];
    __shared__ float sMs[8];
    if (threadIdx.x < 8){
        sc[threadIdx.x] = g_gate[threadIdx.x] / g_Z[threadIdx.x];
        float m = fdec(g_mkey[threadIdx.x]) + fdec(g_mkey[8 + threadIdx.x]);
        sMs[threadIdx.x] = (m > 0.f) ? m : 0.01f*m;
    }
    __syncthreads();
    int warp = threadIdx.x >> 5, lane = threadIdx.x & 31;
    int c = blockIdx.x*8 + warp;
    if (c >= NNODES) return;
    int p0 = g_colptr[c], p1 = g_colptr[c+1];
    if (p0 == p1) return;

    int l4 = lane & 15;                   // lane owns 4 contiguous floats
    const float* wp = g_Wh + (size_t)c*NH;
    float4 w4[8];
#pragma unroll
    for (int h = 0; h < 8; h++)
        w4[h] = *reinterpret_cast<const float4*>(wp + h*64 + 4*l4);

    int hh = lane & 7;
    float sd = g_s[c*16 + 8 + hh];
    float ch = sc[hh];
    float Mh = sMs[hh];
    int half = lane >> 4;                 // 0: edge p, 1: edge p+1

    int p = p0;
    for (; p + 2 <= p1; p += 2){
        float wv = 0.f;
        if (l4 < 8){
            int rowv = g_srow[p + half];
            float t = g_s[rowv*16 + hh] + sd;
            t = (t > 0.f) ? t : 0.01f*t;
            wv = ch * __expf(t - Mh);
        }
        float m0 = 0.f, m1 = 0.f, m2 = 0.f, m3 = 0.f;
#pragma unroll
        for (int h = 0; h < 8; h++){
            float w = __shfl_sync(0xffffffffu, wv, (half << 4) + h);
            m0 += w * w4[h].x;
            m1 += w * w4[h].y;
            m2 += w * w4[h].z;
            m3 += w * w4[h].w;
        }
        int tgt = g_tgt[p + half];
        *reinterpret_cast<float4*>(g_buf + (size_t)tgt*64 + 4*l4) = make_float4(m0,m1,m2,m3);
    }
    if (p < p1){
        float wv = 0.f;
        if (lane < 8){
            int rowv = g_srow[p];
            float t = g_s[rowv*16 + hh] + sd;
            t = (t > 0.f) ? t : 0.01f*t;
            wv = ch * __expf(t - Mh);
        }
        float m0 = 0.f, m1 = 0.f, m2 = 0.f, m3 = 0.f;
#pragma unroll
        for (int h = 0; h < 8; h++){
            float w = __shfl_sync(0xffffffffu, wv, h);
            m0 += w * w4[h].x;
            m1 += w * w4[h].y;
            m2 += w * w4[h].z;
            m3 += w * w4[h].w;
        }
        int tgt = g_tgt[p];
        if (lane < 16)
            *reinterpret_cast<float4*>(g_buf + (size_t)tgt*64 + 4*l4) = make_float4(m0,m1,m2,m3);
    }
}

// ---------------- phase B: contiguous segment sum, direct store ----------------
__global__ __launch_bounds__(256) void k_gather(float* __restrict__ out){
    int warp = threadIdx.x >> 5, lane = threadIdx.x & 31;
    int r = blockIdx.x*8 + warp;
    if (r >= NNODES) return;
    int p0 = g_rowptr[r], p1 = g_rowptr[r+1];
    float a0 = 0.f, a1 = 0.f, b0 = 0.f, b1 = 0.f;
    int p = p0;
    for (; p + 2 <= p1; p += 2){
        const float* m0 = g_buf + (size_t)p*64;
        const float* m1 = g_buf + (size_t)(p+1)*64;
        a0 += m0[lane];
        a1 += m0[32 + lane];
        b0 += m1[lane];
        b1 += m1[32 + lane];
    }
    if (p < p1){
        const float* m0 = g_buf + (size_t)p*64;
        a0 += m0[lane];
        a1 += m0[32 + lane];
    }
    out[(size_t)r*64 + lane]      = a0 + b0;
    out[(size_t)r*64 + 32 + lane] = a1 + b1;
}

// ---------------- launch ----------------
extern "C" void kernel_launch(void* const* d_in, const int* in_sizes, int n_in,
                              void* d_out, int out_size){
    const float* x    = (const float*)d_in[0];
    const int*   ei   = (const int*)  d_in[1];
    const float* W    = (const float*)d_in[2];
    const float* b    = (const float*)d_in[3];
    const float* a    = (const float*)d_in[4];
    const float* gate = (const float*)d_in[5];
    float* out = (float*)d_out;

    cudaFuncSetAttribute(k_big, cudaFuncAttributeMaxDynamicSharedMemorySize, SMEM_BIG);

    k_setup<<<(NPAD*IN_DIM/4 + 255)/256, 256>>>(x, ei, W, gate);
    dim3 gs1((NNODES + 255)/256, 2);
    k_scan1<<<gs1, 256>>>();
    k_scan2<<<2, 256>>>();
    k_scan3<<<gs1, 256>>>();
    dim3 gg(4, NPAD/128);
    k_big<<<gg, 256, SMEM_BIG>>>(b, a, ei);
    k_Z<<<NEDGES/256, 256>>>(ei);
    k_msg<<<(NNODES + 7)/8, 256>>>();
    k_gather<<<(NNODES + 7)/8, 256>>>(out);
}

// round 9
// speedup vs baseline: 1.2827x; 1.2827x over previous
#include <cuda_runtime.h>
#include <cuda_bf16.h>
#include <cuda_fp16.h>
#include <stdint.h>

#define NNODES 50000
#define NPAD   50048            // 391 * 128
#define NEDGES 800000
#define IN_DIM 256
#define HEADS  8
#define NH     512

// ---------------- device scratch ----------------
__device__ __align__(128) __nv_bfloat16 g_Ah[(size_t)NPAD*IN_DIM];
__device__ __align__(128) __nv_bfloat16 g_Al[(size_t)NPAD*IN_DIM];
__device__ __align__(128) __nv_bfloat16 g_Bth[NH*IN_DIM];
__device__ __align__(128) __nv_bfloat16 g_Btl[NH*IN_DIM];
__device__ __align__(128) __half g_Wh16[(size_t)NNODES*NH];   // 51.2 MB (fp16 Wh)
__device__ __align__(16)  float g_s[NNODES*16];
__device__ unsigned g_mkey[16];
__device__ float g_Z[HEADS];
__device__ float g_gate[HEADS];
__device__ int g_cnt[NNODES];          // zeroed by scan1 for next run
__device__ int g_colptr[NNODES+1];
__device__ int g_cur[NNODES];
__device__ int g_bsum[256];
__device__ int g_srow[NEDGES];

// ---------------- helpers ----------------
__device__ __forceinline__ unsigned fkey(float f){
    unsigned b = __float_as_uint(f);
    return (b & 0x80000000u) ? ~b : (b | 0x80000000u);
}
__device__ __forceinline__ float fdec(unsigned k){
    return (k & 0x80000000u) ? __uint_as_float(k ^ 0x80000000u) : __uint_as_float(~k);
}
__device__ __forceinline__ uint32_t s2u(const void* p){
    return (uint32_t)__cvta_generic_to_shared(p);
}
__device__ __forceinline__ void cpa16(uint32_t dst, const void* src){
    asm volatile("cp.async.cg.shared.global [%0], [%1], 16;" :: "r"(dst), "l"(src));
}
__device__ __forceinline__ void ldsm4(uint32_t* r, uint32_t addr){
    asm volatile("ldmatrix.sync.aligned.m8n8.x4.shared.b16 {%0,%1,%2,%3}, [%4];"
        : "=r"(r[0]), "=r"(r[1]), "=r"(r[2]), "=r"(r[3]) : "r"(addr));
}
__device__ __forceinline__ void mma_bf16(float* d, const uint32_t* a, uint32_t b0, uint32_t b1){
    asm volatile("mma.sync.aligned.m16n8k16.row.col.f32.bf16.bf16.f32 "
        "{%0,%1,%2,%3},{%4,%5,%6,%7},{%8,%9},{%0,%1,%2,%3};"
        : "+f"(d[0]), "+f"(d[1]), "+f"(d[2]), "+f"(d[3])
        : "r"(a[0]), "r"(a[1]), "r"(a[2]), "r"(a[3]), "r"(b0), "r"(b1));
}

// ---------------- fused setup: out-zero, misc-zero, convert, prep, edge-count ----------------
__global__ void k_setup(const float* __restrict__ x, const int* __restrict__ ei,
                        const float* __restrict__ W, const float* __restrict__ gate,
                        float* __restrict__ out){
    int tid = blockIdx.x*blockDim.x + threadIdx.x;
    if (tid < 8)  g_Z[tid] = 0.f;
    if (tid < 16) g_mkey[tid] = 0u;
    if (tid == 0){
        float m = -1e30f;
        for (int h = 0; h < HEADS; h++) m = fmaxf(m, gate[h]);
        float ex[HEADS]; float z = 0.f;
        for (int h = 0; h < HEADS; h++){ ex[h] = __expf(gate[h]-m); z += ex[h]; }
        for (int h = 0; h < HEADS; h++) g_gate[h] = ex[h]/z;
    }
    // zero output
    if (tid < NNODES*16)
        reinterpret_cast<float4*>(out)[tid] = make_float4(0.f,0.f,0.f,0.f);
    // edge count for CSC
    if (tid < NEDGES) atomicAdd(&g_cnt[ei[NEDGES + tid]], 1);
    // W transpose to Bt[n][d] bf16 hi/lo
    if (tid < NH*IN_DIM){
        int n = tid >> 8, d = tid & 255;
        int h = n >> 6, o = n & 63;
        float v = W[(size_t)h*IN_DIM*64 + d*64 + o];
        __nv_bfloat16 hb = __float2bfloat16(v);
        __nv_bfloat16 lb = __float2bfloat16(v - __bfloat162float(hb));
        g_Bth[tid] = hb;
        g_Btl[tid] = lb;
    }
    // x -> bf16 hi/lo, padded
    if (tid < NPAD*IN_DIM/4){
        int base = tid*4;
        int row = base / IN_DIM;
        float4 v = make_float4(0.f,0.f,0.f,0.f);
        if (row < NNODES) v = *reinterpret_cast<const float4*>(x + base);
        float vv[4] = {v.x, v.y, v.z, v.w};
        unsigned short hb[4], lb[4];
#pragma unroll
        for (int j = 0; j < 4; j++){
            __nv_bfloat16 h = __float2bfloat16(vv[j]);
            __nv_bfloat16 l = __float2bfloat16(vv[j] - __bfloat162float(h));
            hb[j] = __bfloat16_as_ushort(h);
            lb[j] = __bfloat16_as_ushort(l);
        }
        uint2 ph = make_uint2((unsigned)hb[0] | ((unsigned)hb[1]<<16),
                              (unsigned)hb[2] | ((unsigned)hb[3]<<16));
        uint2 pl = make_uint2((unsigned)lb[0] | ((unsigned)lb[1]<<16),
                              (unsigned)lb[2] | ((unsigned)lb[3]<<16));
        *reinterpret_cast<uint2*>(reinterpret_cast<char*>(g_Ah) + (size_t)base*2) = ph;
        *reinterpret_cast<uint2*>(reinterpret_cast<char*>(g_Al) + (size_t)base*2) = pl;
    }
}

// ---------------- CSC scans (scan1 + merged scan23) ----------------
__global__ void k_scan1(){
    __shared__ int sd[256];
    int tid = threadIdx.x;
    int i = blockIdx.x*256 + tid;
    int v = (i < NNODES) ? g_cnt[i] : 0;
    if (i < NNODES) g_cnt[i] = 0;          // re-zero for next run
    sd[tid] = v; __syncthreads();
    for (int off = 1; off < 256; off <<= 1){
        int t = (tid >= off) ? sd[tid - off] : 0;
        __syncthreads();
        sd[tid] += t;
        __syncthreads();
    }
    if (i < NNODES) g_colptr[i] = sd[tid] - v;   // block-local exclusive prefix
    if (tid == 255) g_bsum[blockIdx.x] = sd[255];
}
// every block redundantly scans the 196 block sums, picks its own offset, applies
__global__ void k_scan23(){
    __shared__ int sd[256];
    __shared__ int s_off;
    int tid = threadIdx.x;
    const int nb = (NNODES + 255)/256;     // 196
    int v = (tid < nb) ? g_bsum[tid] : 0;
    sd[tid] = v; __syncthreads();
    for (int off = 1; off < 256; off <<= 1){
        int t = (tid >= off) ? sd[tid - off] : 0;
        __syncthreads();
        sd[tid] += t;
        __syncthreads();
    }
    if (tid == (int)blockIdx.x) s_off = sd[tid] - v;   // exclusive offset of this block
    __syncthreads();
    int i = blockIdx.x*256 + tid;
    if (i < NNODES){
        int p = g_colptr[i] + s_off;
        g_colptr[i] = p;
        g_cur[i]    = p;
    }
    if (blockIdx.x == 0 && tid == 0) g_colptr[NNODES] = NEDGES;
}

// ---------------- big kernel: bf16 3-pass HMMA GEMM + reorder in prologue ----------------
#define OFF_A    0                      // 4 stages x 8192
#define OFF_B    32768                  // 4 stages x 8192
#define OFF_BIAS 65536                  // 512 f
#define OFF_SA   67584                  // 1024 f
#define OFF_SSM  71680                  // 128*16 f
#define OFF_SMK  79872                  // 16 u32
#define SMEM_BIG 79936

__device__ __forceinline__ void load_tile(uint32_t dstbase, const __nv_bfloat16* __restrict__ src,
                                          int tid){
#pragma unroll
    for (int i = 0; i < 2; i++){
        int idx = tid + i*256;
        int r = idx >> 2, q = idx & 3;
        uint32_t off = (uint32_t)(r*64 + ((q ^ ((r >> 1) & 3)) << 4));
        cpa16(dstbase + off, src + (size_t)r*IN_DIM + q*8);
    }
}

__device__ __forceinline__ void gemm_compute(uint32_t sAb, uint32_t sBb,
                                             int wm, int wn, int lane, float d[4][4][4]){
#pragma unroll
    for (int ks = 0; ks < 2; ks++){
        uint32_t af[4][4], bf[2][4];
        int q = ks*2 + (lane >> 4);
#pragma unroll
        for (int mi = 0; mi < 4; mi++){
            int row = wm + mi*16 + (lane & 15);
            ldsm4(af[mi], sAb + row*64 + ((q ^ ((row >> 1) & 3)) << 4));
        }
#pragma unroll
        for (int bi = 0; bi < 2; bi++){
            int row = wn + bi*16 + (lane & 15);
            ldsm4(bf[bi], sBb + row*64 + ((q ^ ((row >> 1) & 3)) << 4));
        }
#pragma unroll
        for (int mi = 0; mi < 4; mi++)
#pragma unroll
            for (int ni = 0; ni < 4; ni++){
                int bi = ni >> 1, sub = ni & 1;
                mma_bf16(d[mi][ni], af[mi], bf[bi][sub], bf[bi][sub + 2]);
            }
    }
}

// grid = (4, 391)
__global__ __launch_bounds__(256,2) void k_big(const float* __restrict__ bias,
                                               const float* __restrict__ a_vec,
                                               const int* __restrict__ ei){
    extern __shared__ char smem[];
    uint32_t sb = s2u(smem);
    float*    s_bias = (float*)(smem + OFF_BIAS);
    float*    s_a    = (float*)(smem + OFF_SA);
    float*    s_sm   = (float*)(smem + OFF_SSM);
    unsigned* s_mk   = (unsigned*)(smem + OFF_SMK);

    int tid = threadIdx.x, wid = tid >> 5, lane = tid & 31;
    int wm = (wid >> 2)*64, wn = (wid & 3)*32;
    int m0 = blockIdx.y*128, n0 = blockIdx.x*128;

    for (int i = tid; i < 512;  i += 256) s_bias[i] = bias[i];
    for (int i = tid; i < 1024; i += 256) s_a[i]    = a_vec[i];
    for (int i = tid; i < 2048; i += 256) s_sm[i]   = 0.f;
    if (tid < 16) s_mk[tid] = 0u;

    float d[4][4][4];
#pragma unroll
    for (int mi = 0; mi < 4; mi++)
#pragma unroll
        for (int ni = 0; ni < 4; ni++)
#pragma unroll
            for (int k = 0; k < 4; k++) d[mi][ni][k] = 0.f;

    const __nv_bfloat16* Abase  = g_Ah  + (size_t)m0*IN_DIM;
    const __nv_bfloat16* Albase = g_Al  + (size_t)m0*IN_DIM;
    const __nv_bfloat16* Bbase  = g_Bth + (size_t)n0*IN_DIM;
    const __nv_bfloat16* Blbase = g_Btl + (size_t)n0*IN_DIM;

    // chunk c (0..23): pass p=c>>3 (0:Ah*Bh 1:Al*Bh 2:Ah*Bl), k-eighth q=c&7
#pragma unroll
    for (int c = 0; c < 3; c++){
        load_tile(sb + OFF_A + c*8192, Abase + c*32, tid);
        load_tile(sb + OFF_B + c*8192, Bbase + c*32, tid);
        asm volatile("cp.async.commit_group;" ::: "memory");
    }

    // CSC reorder: 512 edges per CTA, hidden behind first chunk loads
    {
        int cta = blockIdx.y*4 + blockIdx.x;
#pragma unroll
        for (int r = 0; r < 2; r++){
            int e = cta*512 + r*256 + tid;
            if (e < NEDGES){
                int row = ei[e], col = ei[NEDGES + e];
                int pos = atomicAdd(&g_cur[col], 1);
                g_srow[pos] = row;
            }
        }
    }

    for (int c = 0; c < 24; c++){
        asm volatile("cp.async.wait_group 2;" ::: "memory");
        __syncthreads();
        int cn = c + 3;
        if (cn < 24){
            int p = cn >> 3, q = cn & 7;
            const __nv_bfloat16* As = ((p == 1) ? Albase : Abase) + q*32;
            const __nv_bfloat16* Bs = ((p == 2) ? Blbase : Bbase) + q*32;
            int st = cn & 3;
            load_tile(sb + OFF_A + st*8192, As, tid);
            load_tile(sb + OFF_B + st*8192, Bs, tid);
        }
        asm volatile("cp.async.commit_group;" ::: "memory");   // possibly empty group
        int st = c & 3;
        gemm_compute(sb + OFF_A + st*8192, sb + OFF_B + st*8192, wm, wn, lane, d);
    }

    // -------- epilogue: bias, fp16 Wh store, fused s-dots + node max --------
    int h = (n0 + wn) >> 6;
    const float* aS = s_a + h*128;
    const float* aD = s_a + h*128 + 64;
    float accS[4][2], accD[4][2];
#pragma unroll
    for (int mi = 0; mi < 4; mi++){ accS[mi][0]=accS[mi][1]=accD[mi][0]=accD[mi][1]=0.f; }

#pragma unroll
    for (int mi = 0; mi < 4; mi++){
#pragma unroll
        for (int ni = 0; ni < 4; ni++){
            int C = wn + ni*8 + (lane & 3)*2;
            int o = C & 63;
            float b0 = s_bias[n0 + C], b1 = s_bias[n0 + C + 1];
#pragma unroll
            for (int rr = 0; rr < 2; rr++){
                float v0 = d[mi][ni][rr*2 + 0] + b0;
                float v1 = d[mi][ni][rr*2 + 1] + b1;
                int R = wm + mi*16 + (lane >> 2) + rr*8;
                int gm = m0 + R;
                if (gm < NNODES){
                    __half2 hv = __floats2half2_rn(v0, v1);
                    *reinterpret_cast<__half2*>(g_Wh16 + (size_t)gm*NH + n0 + C) = hv;
                }
                accS[mi][rr] += v0*aS[o] + v1*aS[o+1];
                accD[mi][rr] += v0*aD[o] + v1*aD[o+1];
            }
        }
    }
#pragma unroll
    for (int mi = 0; mi < 4; mi++)
#pragma unroll
        for (int rr = 0; rr < 2; rr++){
            float vs = accS[mi][rr], vd = accD[mi][rr];
            vs += __shfl_xor_sync(0xffffffffu, vs, 1);
            vs += __shfl_xor_sync(0xffffffffu, vs, 2);
            vd += __shfl_xor_sync(0xffffffffu, vd, 1);
            vd += __shfl_xor_sync(0xffffffffu, vd, 2);
            if ((lane & 3) == 0){
                int R = wm + mi*16 + (lane >> 2) + rr*8;
                atomicAdd(&s_sm[R*16 + h],     vs);
                atomicAdd(&s_sm[R*16 + 8 + h], vd);
            }
        }
    __syncthreads();
    int h0 = n0 >> 6;
    for (int i = tid; i < 512; i += 256){
        int r = i >> 2, jj = i & 3;
        int j = h0 + (jj & 1) + (jj >> 1)*8;
        int gm = m0 + r;
        if (gm < NNODES){
            float v = s_sm[r*16 + j];
            g_s[gm*16 + j] = v;
            atomicMax(&s_mk[j], fkey(v));
        }
    }
    __syncthreads();
    if (tid < 4){
        int j = h0 + (tid & 1) + (tid >> 1)*8;
        unsigned k = s_mk[j];
        if (k) atomicMax(&g_mkey[j], k);
    }
}

// ---------------- per-head Z ----------------
__global__ void k_Z(const int* __restrict__ ei){
    __shared__ float sM[8];
    __shared__ float ssum[8];
    if (threadIdx.x < 8){
        float m = fdec(g_mkey[threadIdx.x]) + fdec(g_mkey[8 + threadIdx.x]);
        sM[threadIdx.x] = (m > 0.f) ? m : 0.01f*m;
        ssum[threadIdx.x] = 0.f;
    }
    __syncthreads();
    int p = blockIdx.x*blockDim.x + threadIdx.x;
    int row = ei[p], col = ei[NEDGES + p];
    float4 s0 = *reinterpret_cast<const float4*>(g_s + row*16);
    float4 s1 = *reinterpret_cast<const float4*>(g_s + row*16 + 4);
    float4 d0 = *reinterpret_cast<const float4*>(g_s + col*16 + 8);
    float4 d1 = *reinterpret_cast<const float4*>(g_s + col*16 + 12);
    float sv[8] = {s0.x,s0.y,s0.z,s0.w,s1.x,s1.y,s1.z,s1.w};
    float dv[8] = {d0.x,d0.y,d0.z,d0.w,d1.x,d1.y,d1.z,d1.w};
    float ex[8];
#pragma unroll
    for (int h = 0; h < 8; h++){
        float t = sv[h] + dv[h];
        t = (t > 0.f) ? t : 0.01f*t;
        ex[h] = __expf(t - sM[h]);
    }
#pragma unroll
    for (int h = 0; h < 8; h++)
#pragma unroll
        for (int off = 16; off; off >>= 1)
            ex[h] += __shfl_xor_sync(0xffffffffu, ex[h], off);
    if ((threadIdx.x & 31) == 0){
#pragma unroll
        for (int h = 0; h < 8; h++) atomicAdd(&ssum[h], ex[h]);
    }
    __syncthreads();
    if (threadIdx.x < 8) atomicAdd(&g_Z[threadIdx.x], ssum[threadIdx.x]);
}

// ---------------- CSC scatter: warp per col, inline w, 2-edge unroll ----------------
__global__ __launch_bounds__(256) void k_scatter(float* __restrict__ out){
    __shared__ float sc[8];
    __shared__ float sMs[8];
    if (threadIdx.x < 8){
        sc[threadIdx.x] = g_gate[threadIdx.x] / g_Z[threadIdx.x];
        float m = fdec(g_mkey[threadIdx.x]) + fdec(g_mkey[8 + threadIdx.x]);
        sMs[threadIdx.x] = (m > 0.f) ? m : 0.01f*m;
    }
    __syncthreads();
    int warp = threadIdx.x >> 5, lane = threadIdx.x & 31;
    int c = blockIdx.x*8 + warp;
    if (c >= NNODES) return;
    int p0 = g_colptr[c], p1 = g_colptr[c+1];
    if (p0 == p1) return;
    const __half* wp = g_Wh16 + (size_t)c*NH;
    float whv[16];
#pragma unroll
    for (int h = 0; h < 8; h++){
        whv[h]     = __half2float(wp[h*64 + lane]);
        whv[8 + h] = __half2float(wp[h*64 + 32 + lane]);
    }
    int hh = lane & 7;
    float sd = g_s[c*16 + 8 + hh];
    float ch = sc[hh];
    float Mh = sMs[hh];

    int p = p0;
    for (; p + 2 <= p1; p += 2){
        float wv = 0.f;
        int rowv = 0;
        if (lane < 16){
            rowv = g_srow[p + (lane >> 3)];
            float t = g_s[rowv*16 + hh] + sd;
            t = (t > 0.f) ? t : 0.01f*t;
            wv = ch * __expf(t - Mh);
        }
        float a00 = 0.f, a01 = 0.f, a10 = 0.f, a11 = 0.f;
#pragma unroll
        for (int h = 0; h < 8; h++){
            float w0 = __shfl_sync(0xffffffffu, wv, h);
            float w1 = __shfl_sync(0xffffffffu, wv, 8 + h);
            a00 += w0 * whv[h];
            a01 += w0 * whv[8 + h];
            a10 += w1 * whv[h];
            a11 += w1 * whv[8 + h];
        }
        int r0 = __shfl_sync(0xffffffffu, rowv, 0);
        int r1 = __shfl_sync(0xffffffffu, rowv, 8);
        atomicAdd(out + (size_t)r0*64 + lane,      a00);
        atomicAdd(out + (size_t)r0*64 + 32 + lane, a01);
        atomicAdd(out + (size_t)r1*64 + lane,      a10);
        atomicAdd(out + (size_t)r1*64 + 32 + lane, a11);
    }
    if (p < p1){
        float wv = 0.f;
        int rowv = 0;
        if (lane < 8){
            rowv = g_srow[p];
            float t = g_s[rowv*16 + hh] + sd;
            t = (t > 0.f) ? t : 0.01f*t;
            wv = ch * __expf(t - Mh);
        }
        float a0 = 0.f, a1 = 0.f;
#pragma unroll
        for (int h = 0; h < 8; h++){
            float w = __shfl_sync(0xffffffffu, wv, h);
            a0 += w * whv[h];
            a1 += w * whv[8 + h];
        }
        int r0 = __shfl_sync(0xffffffffu, rowv, 0);
        atomicAdd(out + (size_t)r0*64 + lane,      a0);
        atomicAdd(out + (size_t)r0*64 + 32 + lane, a1);
    }
}

// ---------------- launch ----------------
extern "C" void kernel_launch(void* const* d_in, const int* in_sizes, int n_in,
                              void* d_out, int out_size){
    const float* x    = (const float*)d_in[0];
    const int*   ei   = (const int*)  d_in[1];
    const float* W    = (const float*)d_in[2];
    const float* b    = (const float*)d_in[3];
    const float* a    = (const float*)d_in[4];
    const float* gate = (const float*)d_in[5];
    float* out = (float*)d_out;

    cudaFuncSetAttribute(k_big, cudaFuncAttributeMaxDynamicSharedMemorySize, SMEM_BIG);

    k_setup<<<(NPAD*IN_DIM/4 + 255)/256, 256>>>(x, ei, W, gate, out);
    k_scan1<<<(NNODES + 255)/256, 256>>>();
    k_scan23<<<(NNODES + 255)/256, 256>>>();
    dim3 gg(4, NPAD/128);
    k_big<<<gg, 256, SMEM_BIG>>>(b, a, ei);    // 6th launch incl. harness memsets -> ncu slot
    k_Z<<<NEDGES/256, 256>>>(ei);
    k_scatter<<<(NNODES + 7)/8, 256>>>(out);
}

// round 10
// speedup vs baseline: 1.3242x; 1.0323x over previous
#include <cuda_runtime.h>
#include <cuda_bf16.h>
#include <cuda_fp16.h>
#include <stdint.h>

#define NNODES 50000
#define NPAD   50048            // 391 * 128
#define NEDGES 800000
#define IN_DIM 256
#define HEADS  8
#define NH     512

// ---------------- device scratch ----------------
__device__ __align__(128) __nv_bfloat16 g_Ah[(size_t)NPAD*IN_DIM];
__device__ __align__(128) __nv_bfloat16 g_Al[(size_t)NPAD*IN_DIM];
__device__ __align__(128) __nv_bfloat16 g_Bth[NH*IN_DIM];
__device__ __align__(128) __nv_bfloat16 g_Btl[NH*IN_DIM];
__device__ __align__(128) __half g_Wh16[(size_t)NNODES*NH];   // 51.2 MB (fp16 Wh)
__device__ __align__(16)  float g_s[NNODES*16];
__device__ unsigned g_mkey[16];
__device__ float g_Z[HEADS];
__device__ float g_gate[HEADS];
__device__ int g_cnt[NNODES];          // zeroed by scan1 for next run
__device__ int g_colptr[NNODES+1];
__device__ int g_cur[NNODES];
__device__ int g_bsum[256];
__device__ int g_srow[NEDGES];

// ---------------- helpers ----------------
__device__ __forceinline__ unsigned fkey(float f){
    unsigned b = __float_as_uint(f);
    return (b & 0x80000000u) ? ~b : (b | 0x80000000u);
}
__device__ __forceinline__ float fdec(unsigned k){
    return (k & 0x80000000u) ? __uint_as_float(k ^ 0x80000000u) : __uint_as_float(~k);
}
__device__ __forceinline__ uint32_t s2u(const void* p){
    return (uint32_t)__cvta_generic_to_shared(p);
}
__device__ __forceinline__ void cpa16(uint32_t dst, const void* src){
    asm volatile("cp.async.cg.shared.global [%0], [%1], 16;" :: "r"(dst), "l"(src));
}
__device__ __forceinline__ void ldsm4(uint32_t* r, uint32_t addr){
    asm volatile("ldmatrix.sync.aligned.m8n8.x4.shared.b16 {%0,%1,%2,%3}, [%4];"
        : "=r"(r[0]), "=r"(r[1]), "=r"(r[2]), "=r"(r[3]) : "r"(addr));
}
__device__ __forceinline__ void mma_bf16(float* d, const uint32_t* a, uint32_t b0, uint32_t b1){
    asm volatile("mma.sync.aligned.m16n8k16.row.col.f32.bf16.bf16.f32 "
        "{%0,%1,%2,%3},{%4,%5,%6,%7},{%8,%9},{%0,%1,%2,%3};"
        : "+f"(d[0]), "+f"(d[1]), "+f"(d[2]), "+f"(d[3])
        : "r"(a[0]), "r"(a[1]), "r"(a[2]), "r"(a[3]), "r"(b0), "r"(b1));
}

// ---------------- fused setup ----------------
__global__ void k_setup(const float* __restrict__ x, const int* __restrict__ ei,
                        const float* __restrict__ W, const float* __restrict__ gate,
                        float* __restrict__ out){
    int tid = blockIdx.x*blockDim.x + threadIdx.x;
    if (tid < 8)  g_Z[tid] = 0.f;
    if (tid < 16) g_mkey[tid] = 0u;
    if (tid == 0){
        float m = -1e30f;
        for (int h = 0; h < HEADS; h++) m = fmaxf(m, gate[h]);
        float ex[HEADS]; float z = 0.f;
        for (int h = 0; h < HEADS; h++){ ex[h] = __expf(gate[h]-m); z += ex[h]; }
        for (int h = 0; h < HEADS; h++) g_gate[h] = ex[h]/z;
    }
    if (tid < NNODES*16)
        reinterpret_cast<float4*>(out)[tid] = make_float4(0.f,0.f,0.f,0.f);
    if (tid < NEDGES) atomicAdd(&g_cnt[ei[NEDGES + tid]], 1);
    if (tid < NH*IN_DIM){
        int n = tid >> 8, d = tid & 255;
        int h = n >> 6, o = n & 63;
        float v = W[(size_t)h*IN_DIM*64 + d*64 + o];
        __nv_bfloat16 hb = __float2bfloat16(v);
        __nv_bfloat16 lb = __float2bfloat16(v - __bfloat162float(hb));
        g_Bth[tid] = hb;
        g_Btl[tid] = lb;
    }
    if (tid < NPAD*IN_DIM/4){
        int base = tid*4;
        int row = base / IN_DIM;
        float4 v = make_float4(0.f,0.f,0.f,0.f);
        if (row < NNODES) v = *reinterpret_cast<const float4*>(x + base);
        float vv[4] = {v.x, v.y, v.z, v.w};
        unsigned short hb[4], lb[4];
#pragma unroll
        for (int j = 0; j < 4; j++){
            __nv_bfloat16 h = __float2bfloat16(vv[j]);
            __nv_bfloat16 l = __float2bfloat16(vv[j] - __bfloat162float(h));
            hb[j] = __bfloat16_as_ushort(h);
            lb[j] = __bfloat16_as_ushort(l);
        }
        uint2 ph = make_uint2((unsigned)hb[0] | ((unsigned)hb[1]<<16),
                              (unsigned)hb[2] | ((unsigned)hb[3]<<16));
        uint2 pl = make_uint2((unsigned)lb[0] | ((unsigned)lb[1]<<16),
                              (unsigned)lb[2] | ((unsigned)lb[3]<<16));
        *reinterpret_cast<uint2*>(reinterpret_cast<char*>(g_Ah) + (size_t)base*2) = ph;
        *reinterpret_cast<uint2*>(reinterpret_cast<char*>(g_Al) + (size_t)base*2) = pl;
    }
}

// ---------------- CSC scans ----------------
__global__ void k_scan1(){
    __shared__ int sd[256];
    int tid = threadIdx.x;
    int i = blockIdx.x*256 + tid;
    int v = (i < NNODES) ? g_cnt[i] : 0;
    if (i < NNODES) g_cnt[i] = 0;
    sd[tid] = v; __syncthreads();
    for (int off = 1; off < 256; off <<= 1){
        int t = (tid >= off) ? sd[tid - off] : 0;
        __syncthreads();
        sd[tid] += t;
        __syncthreads();
    }
    if (i < NNODES) g_colptr[i] = sd[tid] - v;
    if (tid == 255) g_bsum[blockIdx.x] = sd[255];
}
__global__ void k_scan23(){
    __shared__ int sd[256];
    __shared__ int s_off;
    int tid = threadIdx.x;
    const int nb = (NNODES + 255)/256;
    int v = (tid < nb) ? g_bsum[tid] : 0;
    sd[tid] = v; __syncthreads();
    for (int off = 1; off < 256; off <<= 1){
        int t = (tid >= off) ? sd[tid - off] : 0;
        __syncthreads();
        sd[tid] += t;
        __syncthreads();
    }
    if (tid == (int)blockIdx.x) s_off = sd[tid] - v;
    __syncthreads();
    int i = blockIdx.x*256 + tid;
    if (i < NNODES){
        int p = g_colptr[i] + s_off;
        g_colptr[i] = p;
        g_cur[i]    = p;
    }
    if (blockIdx.x == 0 && tid == 0) g_colptr[NNODES] = NEDGES;
}

// ---------------- big kernel: bf16 3-pass HMMA, K-chunk=64, 3-stage pipe ----------------
#define ST       16384                  // bytes per stage per operand (128 rows x 128B)
#define OFF_A    0                      // 3 stages
#define OFF_B    49152                  // 3 stages
#define OFF_BIAS 98304                  // 512 f
#define OFF_SA   100352                 // 1024 f
#define OFF_SSM  104448                 // 128*16 f
#define OFF_SMK  112640                 // 16 u32
#define SMEM_BIG 112704

// 128 rows x 64 cols bf16 (128B rows), swizzle chunk = q ^ (r&7)
__device__ __forceinline__ void load_tile64(uint32_t dstbase, const __nv_bfloat16* __restrict__ src,
                                            int tid){
#pragma unroll
    for (int i = 0; i < 4; i++){
        int idx = tid + i*256;
        int r = idx >> 3, q = idx & 7;
        uint32_t off = (uint32_t)(r*128 + ((q ^ (r & 7)) << 4));
        cpa16(dstbase + off, src + (size_t)r*IN_DIM + q*8);
    }
}

__device__ __forceinline__ void gemm_compute64(uint32_t sAb, uint32_t sBb,
                                               int wm, int wn, int lane, float d[4][4][4]){
    int lr = lane & 15;
    int qh = lane >> 4;
    // loop-invariant row terms
    uint32_t arow[4], brow[2];
    int asw[4], bsw[2];
#pragma unroll
    for (int mi = 0; mi < 4; mi++){
        int row = wm + mi*16 + lr;
        arow[mi] = sAb + row*128;
        asw[mi]  = row & 7;
    }
#pragma unroll
    for (int bi = 0; bi < 2; bi++){
        int row = wn + bi*16 + lr;
        brow[bi] = sBb + row*128;
        bsw[bi]  = row & 7;
    }
#pragma unroll
    for (int ks = 0; ks < 4; ks++){
        int q = ks*2 + qh;
        uint32_t af[4][4], bf[2][4];
#pragma unroll
        for (int mi = 0; mi < 4; mi++)
            ldsm4(af[mi], arow[mi] + ((q ^ asw[mi]) << 4));
#pragma unroll
        for (int bi = 0; bi < 2; bi++)
            ldsm4(bf[bi], brow[bi] + ((q ^ bsw[bi]) << 4));
#pragma unroll
        for (int mi = 0; mi < 4; mi++)
#pragma unroll
            for (int ni = 0; ni < 4; ni++){
                int bi = ni >> 1, sub = ni & 1;
                mma_bf16(d[mi][ni], af[mi], bf[bi][sub], bf[bi][sub + 2]);
            }
    }
}

// grid = (4, 391)
__global__ __launch_bounds__(256,2) void k_big(const float* __restrict__ bias,
                                               const float* __restrict__ a_vec,
                                               const int* __restrict__ ei){
    extern __shared__ char smem[];
    uint32_t sb = s2u(smem);
    float*    s_bias = (float*)(smem + OFF_BIAS);
    float*    s_a    = (float*)(smem + OFF_SA);
    float*    s_sm   = (float*)(smem + OFF_SSM);
    unsigned* s_mk   = (unsigned*)(smem + OFF_SMK);

    int tid = threadIdx.x, wid = tid >> 5, lane = tid & 31;
    int wm = (wid >> 2)*64, wn = (wid & 3)*32;
    int m0 = blockIdx.y*128, n0 = blockIdx.x*128;

    for (int i = tid; i < 512;  i += 256) s_bias[i] = bias[i];
    for (int i = tid; i < 1024; i += 256) s_a[i]    = a_vec[i];
    for (int i = tid; i < 2048; i += 256) s_sm[i]   = 0.f;
    if (tid < 16) s_mk[tid] = 0u;

    float d[4][4][4];
#pragma unroll
    for (int mi = 0; mi < 4; mi++)
#pragma unroll
        for (int ni = 0; ni < 4; ni++)
#pragma unroll
            for (int k = 0; k < 4; k++) d[mi][ni][k] = 0.f;

    const __nv_bfloat16* Abase  = g_Ah  + (size_t)m0*IN_DIM;
    const __nv_bfloat16* Albase = g_Al  + (size_t)m0*IN_DIM;
    const __nv_bfloat16* Bbase  = g_Bth + (size_t)n0*IN_DIM;
    const __nv_bfloat16* Blbase = g_Btl + (size_t)n0*IN_DIM;

    // chunk c (0..11): pass p=c>>2 (0:Ah*Bh 1:Al*Bh 2:Ah*Bl), K-quarter q4=c&3 (64 cols)
    // prologue: chunks 0,1 into stages 0,1
#pragma unroll
    for (int c = 0; c < 2; c++){
        load_tile64(sb + OFF_A + c*ST, Abase + c*64, tid);
        load_tile64(sb + OFF_B + c*ST, Bbase + c*64, tid);
        asm volatile("cp.async.commit_group;" ::: "memory");
    }

    // CSC reorder: 512 edges per CTA, hidden behind prologue loads
    {
        int cta = blockIdx.y*4 + blockIdx.x;
#pragma unroll
        for (int r = 0; r < 2; r++){
            int e = cta*512 + r*256 + tid;
            if (e < NEDGES){
                int row = ei[e], col = ei[NEDGES + e];
                int pos = atomicAdd(&g_cur[col], 1);
                g_srow[pos] = row;
            }
        }
    }

    for (int c = 0; c < 12; c++){
        asm volatile("cp.async.wait_group 1;" ::: "memory");
        __syncthreads();
        int cn = c + 2;
        if (cn < 12){
            int p = cn >> 2, q4 = cn & 3;
            const __nv_bfloat16* As = ((p == 1) ? Albase : Abase) + q4*64;
            const __nv_bfloat16* Bs = ((p == 2) ? Blbase : Bbase) + q4*64;
            int st = cn % 3;
            load_tile64(sb + OFF_A + st*ST, As, tid);
            load_tile64(sb + OFF_B + st*ST, Bs, tid);
        }
        asm volatile("cp.async.commit_group;" ::: "memory");   // possibly empty group
        int st = c % 3;
        gemm_compute64(sb + OFF_A + st*ST, sb + OFF_B + st*ST, wm, wn, lane, d);
    }

    // -------- epilogue: bias, fp16 Wh store, fused s-dots + node max --------
    int h = (n0 + wn) >> 6;
    const float* aS = s_a + h*128;
    const float* aD = s_a + h*128 + 64;
    float accS[4][2], accD[4][2];
#pragma unroll
    for (int mi = 0; mi < 4; mi++){ accS[mi][0]=accS[mi][1]=accD[mi][0]=accD[mi][1]=0.f; }

#pragma unroll
    for (int mi = 0; mi < 4; mi++){
#pragma unroll
        for (int ni = 0; ni < 4; ni++){
            int C = wn + ni*8 + (lane & 3)*2;
            int o = C & 63;
            float b0 = s_bias[n0 + C], b1 = s_bias[n0 + C + 1];
#pragma unroll
            for (int rr = 0; rr < 2; rr++){
                float v0 = d[mi][ni][rr*2 + 0] + b0;
                float v1 = d[mi][ni][rr*2 + 1] + b1;
                int R = wm + mi*16 + (lane >> 2) + rr*8;
                int gm = m0 + R;
                if (gm < NNODES){
                    __half2 hv = __floats2half2_rn(v0, v1);
                    *reinterpret_cast<__half2*>(g_Wh16 + (size_t)gm*NH + n0 + C) = hv;
                }
                accS[mi][rr] += v0*aS[o] + v1*aS[o+1];
                accD[mi][rr] += v0*aD[o] + v1*aD[o+1];
            }
        }
    }
#pragma unroll
    for (int mi = 0; mi < 4; mi++)
#pragma unroll
        for (int rr = 0; rr < 2; rr++){
            float vs = accS[mi][rr], vd = accD[mi][rr];
            vs += __shfl_xor_sync(0xffffffffu, vs, 1);
            vs += __shfl_xor_sync(0xffffffffu, vs, 2);
            vd += __shfl_xor_sync(0xffffffffu, vd, 1);
            vd += __shfl_xor_sync(0xffffffffu, vd, 2);
            if ((lane & 3) == 0){
                int R = wm + mi*16 + (lane >> 2) + rr*8;
                atomicAdd(&s_sm[R*16 + h],     vs);
                atomicAdd(&s_sm[R*16 + 8 + h], vd);
            }
        }
    __syncthreads();
    int h0 = n0 >> 6;
    for (int i = tid; i < 512; i += 256){
        int r = i >> 2, jj = i & 3;
        int j = h0 + (jj & 1) + (jj >> 1)*8;
        int gm = m0 + r;
        if (gm < NNODES){
            float v = s_sm[r*16 + j];
            g_s[gm*16 + j] = v;
            atomicMax(&s_mk[j], fkey(v));
        }
    }
    __syncthreads();
    if (tid < 4){
        int j = h0 + (tid & 1) + (tid >> 1)*8;
        unsigned k = s_mk[j];
        if (k) atomicMax(&g_mkey[j], k);
    }
}

// ---------------- per-head Z ----------------
__global__ void k_Z(const int* __restrict__ ei){
    __shared__ float sM[8];
    __shared__ float ssum[8];
    if (threadIdx.x < 8){
        float m = fdec(g_mkey[threadIdx.x]) + fdec(g_mkey[8 + threadIdx.x]);
        sM[threadIdx.x] = (m > 0.f) ? m : 0.01f*m;
        ssum[threadIdx.x] = 0.f;
    }
    __syncthreads();
    int p = blockIdx.x*blockDim.x + threadIdx.x;
    int row = ei[p], col = ei[NEDGES + p];
    float4 s0 = *reinterpret_cast<const float4*>(g_s + row*16);
    float4 s1 = *reinterpret_cast<const float4*>(g_s + row*16 + 4);
    float4 d0 = *reinterpret_cast<const float4*>(g_s + col*16 + 8);
    float4 d1 = *reinterpret_cast<const float4*>(g_s + col*16 + 12);
    float sv[8] = {s0.x,s0.y,s0.z,s0.w,s1.x,s1.y,s1.z,s1.w};
    float dv[8] = {d0.x,d0.y,d0.z,d0.w,d1.x,d1.y,d1.z,d1.w};
    float ex[8];
#pragma unroll
    for (int h = 0; h < 8; h++){
        float t = sv[h] + dv[h];
        t = (t > 0.f) ? t : 0.01f*t;
        ex[h] = __expf(t - sM[h]);
    }
#pragma unroll
    for (int h = 0; h < 8; h++)
#pragma unroll
        for (int off = 16; off; off >>= 1)
            ex[h] += __shfl_xor_sync(0xffffffffu, ex[h], off);
    if ((threadIdx.x & 31) == 0){
#pragma unroll
        for (int h = 0; h < 8; h++) atomicAdd(&ssum[h], ex[h]);
    }
    __syncthreads();
    if (threadIdx.x < 8) atomicAdd(&g_Z[threadIdx.x], ssum[threadIdx.x]);
}

// ---------------- CSC scatter: warp per col, inline w, 2-edge unroll ----------------
__global__ __launch_bounds__(256) void k_scatter(float* __restrict__ out){
    __shared__ float sc[8];
    __shared__ float sMs[8];
    if (threadIdx.x < 8){
        sc[threadIdx.x] = g_gate[threadIdx.x] / g_Z[threadIdx.x];
        float m = fdec(g_mkey[threadIdx.x]) + fdec(g_mkey[8 + threadIdx.x]);
        sMs[threadIdx.x] = (m > 0.f) ? m : 0.01f*m;
    }
    __syncthreads();
    int warp = threadIdx.x >> 5, lane = threadIdx.x & 31;
    int c = blockIdx.x*8 + warp;
    if (c >= NNODES) return;
    int p0 = g_colptr[c], p1 = g_colptr[c+1];
    if (p0 == p1) return;
    const __half* wp = g_Wh16 + (size_t)c*NH;
    float whv[16];
#pragma unroll
    for (int h = 0; h < 8; h++){
        whv[h]     = __half2float(wp[h*64 + lane]);
        whv[8 + h] = __half2float(wp[h*64 + 32 + lane]);
    }
    int hh = lane & 7;
    float sd = g_s[c*16 + 8 + hh];
    float ch = sc[hh];
    float Mh = sMs[hh];

    int p = p0;
    for (; p + 2 <= p1; p += 2){
        float wv = 0.f;
        int rowv = 0;
        if (lane < 16){
            rowv = g_srow[p + (lane >> 3)];
            float t = g_s[rowv*16 + hh] + sd;
            t = (t > 0.f) ? t : 0.01f*t;
            wv = ch * __expf(t - Mh);
        }
        float a00 = 0.f, a01 = 0.f, a10 = 0.f, a11 = 0.f;
#pragma unroll
        for (int h = 0; h < 8; h++){
            float w0 = __shfl_sync(0xffffffffu, wv, h);
            float w1 = __shfl_sync(0xffffffffu, wv, 8 + h);
            a00 += w0 * whv[h];
            a01 += w0 * whv[8 + h];
            a10 += w1 * whv[h];
            a11 += w1 * whv[8 + h];
        }
        int r0 = __shfl_sync(0xffffffffu, rowv, 0);
        int r1 = __shfl_sync(0xffffffffu, rowv, 8);
        atomicAdd(out + (size_t)r0*64 + lane,      a00);
        atomicAdd(out + (size_t)r0*64 + 32 + lane, a01);
        atomicAdd(out + (size_t)r1*64 + lane,      a10);
        atomicAdd(out + (size_t)r1*64 + 32 + lane, a11);
    }
    if (p < p1){
        float wv = 0.f;
        int rowv = 0;
        if (lane < 8){
            rowv = g_srow[p];
            float t = g_s[rowv*16 + hh] + sd;
            t = (t > 0.f) ? t : 0.01f*t;
            wv = ch * __expf(t - Mh);
        }
        float a0 = 0.f, a1 = 0.f;
#pragma unroll
        for (int h = 0; h < 8; h++){
            float w = __shfl_sync(0xffffffffu, wv, h);
            a0 += w * whv[h];
            a1 += w * whv[8 + h];
        }
        int r0 = __shfl_sync(0xffffffffu, rowv, 0);
        atomicAdd(out + (size_t)r0*64 + lane,      a0);
        atomicAdd(out + (size_t)r0*64 + 32 + lane, a1);
    }
}

// ---------------- launch ----------------
extern "C" void kernel_launch(void* const* d_in, const int* in_sizes, int n_in,
                              void* d_out, int out_size){
    const float* x    = (const float*)d_in[0];
    const int*   ei   = (const int*)  d_in[1];
    const float* W    = (const float*)d_in[2];
    const float* b    = (const float*)d_in[3];
    const float* a    = (const float*)d_in[4];
    const float* gate = (const float*)d_in[5];
    float* out = (float*)d_out;

    cudaFuncSetAttribute(k_big, cudaFuncAttributeMaxDynamicSharedMemorySize, SMEM_BIG);

    k_setup<<<(NPAD*IN_DIM/4 + 255)/256, 256>>>(x, ei, W, gate, out);
    k_scan1<<<(NNODES + 255)/256, 256>>>();
    k_scan23<<<(NNODES + 255)/256, 256>>>();
    dim3 gg(4, NPAD/128);
    k_big<<<gg, 256, SMEM_BIG>>>(b, a, ei);    // ncu captured slot
    k_Z<<<NEDGES/256, 256>>>(ei);
    k_scatter<<<(NNODES + 7)/8, 256>>>(out);
}